// round 5
// baseline (speedup 1.0000x reference)
#include <cuda_runtime.h>
#include <cuda_fp16.h>

#define NT   256
#define SEQ  1024
#define NB   64

// Precomputed exp(transitions) packed by row-pairs:
// g_Epack[k*NT + j] = half2( exp(T[2k][j]), exp(T[2k+1][j]) )
__device__ __half2 g_Epack[128 * NT];

// Runtime dtype-layout flags (harness may widen bool->int32, and JAX demotes
// int64->int32; detect actual bit layout instead of trusting declarations).
__device__ int g_tag_shift;   // 0: tags stored as int32;  1: stored as int64 (read low word)
__device__ int g_msk_shift;   // 0: mask stored as uint8;  2: stored as int32 (read LSB byte)

__global__ void crf_detect_kernel(const int* __restrict__ tags_raw,
                                  const unsigned int* __restrict__ mask_raw) {
    if (threadIdx.x != 0 || blockIdx.x != 0) return;
    // tags: int64 layout => every odd 32-bit word is the (zero) high half.
    int any_odd = 0;
    for (int t = 0; t < 512; ++t) any_odd |= tags_raw[2 * t + 1];
    g_tag_shift = (any_odd == 0) ? 1 : 0;
    // mask: uint8 layout with any true bit in bytes 1..3 of a word => uint8.
    int upper = 0;
    for (int w = 0; w < 1024; ++w) upper |= (int)(mask_raw[w] & 0xFFFFFF00u);
    g_msk_shift = (upper == 0) ? 2 : 0;
}

__global__ void crf_exp_kernel(const float* __restrict__ trans) {
    int idx = blockIdx.x * blockDim.x + threadIdx.x;  // 0 .. 32767
    int k = idx >> 8;
    int j = idx & (NT - 1);
    float e0 = __expf(trans[(2 * k) * NT + j]);
    float e1 = __expf(trans[(2 * k + 1) * NT + j]);
    g_Epack[idx] = __floats2half2_rn(e0, e1);
}

__global__ __launch_bounds__(256, 1)
void crf_fwd_kernel(const float* __restrict__ inputs,
                    const void* __restrict__ tags_v,
                    const void* __restrict__ mask_v,
                    const float* __restrict__ trans,
                    const float* __restrict__ start_t,
                    const float* __restrict__ stop_t,
                    float* __restrict__ out) {
    __shared__ __align__(16) __half aexp_h[NT];
    __shared__ float wred[8];

    const int j    = threadIdx.x;
    const int b    = blockIdx.x;
    const int lane = j & 31;
    const int wid  = j >> 5;

    const int tsh = g_tag_shift;   // word-index shift for tags
    const int msh = g_msk_shift;   // byte-index shift for mask

    const int*           tg32 = (const int*)tags_v;           // low word of each tag
    const unsigned char* mk8  = (const unsigned char*)mask_v; // LSB byte of each mask elem

    // This thread's column of E in registers: 128 half2 = rows (2k, 2k+1), col j.
    __half2 Ereg[128];
#pragma unroll
    for (int k = 0; k < 128; ++k) Ereg[k] = g_Epack[k * NT + j];

    const float* x = inputs + (size_t)b * SEQ * NT;
    const size_t rowbase = (size_t)b * SEQ;

    float alpha = start_t[j] + x[j];

    for (int t = 1; t < SEQ; ++t) {
        // ---- block max of alpha ----
        float m = alpha;
#pragma unroll
        for (int off = 16; off > 0; off >>= 1)
            m = fmaxf(m, __shfl_xor_sync(0xffffffffu, m, off));
        if (lane == 0) wred[wid] = m;
        __syncthreads();
        float M = wred[0];
#pragma unroll
        for (int w = 1; w < 8; ++w) M = fmaxf(M, wred[w]);

        // a_j = exp(alpha_j - M)  (<= 1, safe in fp16)
        aexp_h[j] = __float2half_rn(__expf(alpha - M));

        // prefetch emission + mask for this step (consumed after the matvec)
        float        emit = x[(size_t)t * NT + j];
        unsigned int msk  = mk8[(rowbase + t) << msh];
        __syncthreads();

        // ---- s_j = sum_i a_i * E[i][j], fp16 HFMA2 with 4 accumulators ----
        __half2 acc0 = __floats2half2_rn(0.f, 0.f);
        __half2 acc1 = acc0, acc2 = acc0, acc3 = acc0;
        const uint4* A4 = reinterpret_cast<const uint4*>(aexp_h);
#pragma unroll
        for (int c = 0; c < 32; ++c) {
            uint4 av = A4[c];
            acc0 = __hfma2(*reinterpret_cast<__half2*>(&av.x), Ereg[4 * c + 0], acc0);
            acc1 = __hfma2(*reinterpret_cast<__half2*>(&av.y), Ereg[4 * c + 1], acc1);
            acc2 = __hfma2(*reinterpret_cast<__half2*>(&av.z), Ereg[4 * c + 2], acc2);
            acc3 = __hfma2(*reinterpret_cast<__half2*>(&av.w), Ereg[4 * c + 3], acc3);
        }
        float2 f0 = __half22float2(acc0);
        float2 f1 = __half22float2(acc1);
        float2 f2 = __half22float2(acc2);
        float2 f3 = __half22float2(acc3);
        float s = ((f0.x + f0.y) + (f1.x + f1.y)) + ((f2.x + f2.y) + (f3.x + f3.y));

        float na = M + __logf(s) + emit;
        alpha = msk ? na : alpha;
    }

    // ---- denominator: logsumexp_j(alpha_j + stop_j) ----
    float v = alpha + stop_t[j];
    float m = v;
#pragma unroll
    for (int off = 16; off > 0; off >>= 1)
        m = fmaxf(m, __shfl_xor_sync(0xffffffffu, m, off));
    __syncthreads();
    if (lane == 0) wred[wid] = m;
    __syncthreads();
    float Md = wred[0];
#pragma unroll
    for (int w = 1; w < 8; ++w) Md = fmaxf(Md, wred[w]);

    float e = __expf(v - Md);
#pragma unroll
    for (int off = 16; off > 0; off >>= 1)
        e += __shfl_xor_sync(0xffffffffu, e, off);
    __syncthreads();
    if (lane == 0) wred[wid] = e;
    __syncthreads();
    float tot = 0.f;
#pragma unroll
    for (int w = 0; w < 8; ++w) tot += wred[w];
    float denom = Md + __logf(tot);

    // ---- numerator (gather score) ----
    float part = 0.f;
    for (int t = j; t < SEQ; t += 256) {
        int   tag = tg32[(rowbase + t) << tsh];
        float mf  = mk8[(rowbase + t) << msh] ? 1.f : 0.f;
        if (t == 0) part += start_t[tag];
        else {
            int ptag = tg32[(rowbase + t - 1) << tsh];
            part += trans[ptag * NT + tag] * mf;
        }
        float em = x[(size_t)t * NT + tag];
        if (t < SEQ - 1) part += em * mf;
        else             part += (stop_t[tag] + em) * mf;
    }
#pragma unroll
    for (int off = 16; off > 0; off >>= 1)
        part += __shfl_xor_sync(0xffffffffu, part, off);
    __syncthreads();
    if (lane == 0) wred[wid] = part;
    __syncthreads();
    if (j == 0) {
        float num = 0.f;
#pragma unroll
        for (int w = 0; w < 8; ++w) num += wred[w];
        out[b] = num - denom;
    }
}

extern "C" void kernel_launch(void* const* d_in, const int* in_sizes, int n_in,
                              void* d_out, int out_size) {
    const float* inputs  = (const float*)d_in[0];
    const void*  tags    = d_in[1];
    const void*  mask    = d_in[2];
    const float* trans   = (const float*)d_in[3];
    const float* start_t = (const float*)d_in[4];
    const float* stop_t  = (const float*)d_in[5];
    float*       out     = (float*)d_out;

    crf_detect_kernel<<<1, 32>>>((const int*)tags, (const unsigned int*)mask);
    crf_exp_kernel<<<128, 256>>>(trans);
    crf_fwd_kernel<<<NB, 256>>>(inputs, tags, mask, trans, start_t, stop_t, out);
}